// round 4
// baseline (speedup 1.0000x reference)
#include <cuda_runtime.h>
#include <cuda_bf16.h>
#include <math.h>
#include <stdint.h>

// Problem constants
#define B_  4
#define L_  2048
#define D_  1024
#define H_  16
#define HD_ 64
#define M_TOT (B_ * L_)          // 8192 rows for all projection GEMMs

typedef unsigned long long u64t;

// ---------------------------------------------------------------------------
// Scratch (allocation-free rule: __device__ globals)
// ---------------------------------------------------------------------------
__device__ float g_Q[(size_t)M_TOT * D_];
__device__ float g_K[(size_t)M_TOT * D_];
__device__ float g_V[(size_t)M_TOT * D_];
__device__ float g_C[(size_t)M_TOT * D_];

// ---------------------------------------------------------------------------
// Packed f32x2 helpers (sm_103a FFMA2 path — only reachable via PTX)
// ---------------------------------------------------------------------------
__device__ __forceinline__ u64t fma2(u64t a, u64t b, u64t c) {
    u64t d;
    asm("fma.rn.f32x2 %0, %1, %2, %3;" : "=l"(d) : "l"(a), "l"(b), "l"(c));
    return d;
}
__device__ __forceinline__ u64t mul2(u64t a, u64t b) {
    u64t d;
    asm("mul.rn.f32x2 %0, %1, %2;" : "=l"(d) : "l"(a), "l"(b));
    return d;
}
__device__ __forceinline__ u64t dup2(float x) {
    u64t d;
    uint32_t u = __float_as_uint(x);
    asm("mov.b64 %0, {%1, %2};" : "=l"(d) : "r"(u), "r"(u));
    return d;
}
__device__ __forceinline__ void unpack2(u64t v, float& lo, float& hi) {
    uint32_t a, b;
    asm("mov.b64 {%0, %1}, %2;" : "=r"(a), "=r"(b) : "l"(v));
    lo = __uint_as_float(a);
    hi = __uint_as_float(b);
}

// ---------------------------------------------------------------------------
// GEMM (packed f32x2, bit-exact fp32, double-buffered):
//   C[m][n] = sum_k A[m][k] * W[n][k] + bias[n]
// A: [M,K] row-major, W: [N,K] row-major (torch Linear weight).
// 128x128 CTA tile, BK=16, 256 threads, 8x8 per-thread micro tile as
// 8 (m) x 4 (packed n-pair) f32x2 FMAs. Two-stage SMEM: LDGs for tile k+1
// issued before computing tile k; one barrier per iteration.
// ---------------------------------------------------------------------------
#define BM 128
#define BN 128
#define BK 16
#define GST (BM + 4)   // SMEM row stride (floats): 132 -> 528B, 16B aligned

__global__ __launch_bounds__(256, 2) void gemm_f32x2_bias(
    const float* __restrict__ A, const float* __restrict__ W,
    const float* __restrict__ bias, float* __restrict__ C,
    int M, int N, int K)
{
    __shared__ float As[2][BK][GST];
    __shared__ float Ws[2][BK][GST];

    const int tid = threadIdx.x;
    const int m0 = blockIdx.y * BM;
    const int n0 = blockIdx.x * BN;
    const int tr = tid >> 4;   // 0..15
    const int tc = tid & 15;   // 0..15

    // Per-thread load coordinates (two 512-element chunks)
    const int lm0 = tid >> 2;                 // row 0..63   (chunk 0)
    const int lm1 = (tid + 256) >> 2;         // row 64..127 (chunk 1)
    const int lkq = (tid & 3) << 2;           // k offset 0,4,8,12

    u64t acc[8][4];
#pragma unroll
    for (int i = 0; i < 8; i++)
#pragma unroll
        for (int j = 0; j < 4; j++) acc[i][j] = 0ull;

    const float* Arow0 = A + (size_t)(m0 + lm0) * K + lkq;
    const float* Arow1 = A + (size_t)(m0 + lm1) * K + lkq;
    const float* Wrow0 = W + (size_t)(n0 + lm0) * K + lkq;
    const float* Wrow1 = W + (size_t)(n0 + lm1) * K + lkq;

    // Prologue: load tile 0 into buffer 0
    {
        float4 va0 = *(const float4*)(Arow0);
        float4 va1 = *(const float4*)(Arow1);
        float4 vw0 = *(const float4*)(Wrow0);
        float4 vw1 = *(const float4*)(Wrow1);
        As[0][lkq + 0][lm0] = va0.x; As[0][lkq + 1][lm0] = va0.y;
        As[0][lkq + 2][lm0] = va0.z; As[0][lkq + 3][lm0] = va0.w;
        As[0][lkq + 0][lm1] = va1.x; As[0][lkq + 1][lm1] = va1.y;
        As[0][lkq + 2][lm1] = va1.z; As[0][lkq + 3][lm1] = va1.w;
        Ws[0][lkq + 0][lm0] = vw0.x; Ws[0][lkq + 1][lm0] = vw0.y;
        Ws[0][lkq + 2][lm0] = vw0.z; Ws[0][lkq + 3][lm0] = vw0.w;
        Ws[0][lkq + 0][lm1] = vw1.x; Ws[0][lkq + 1][lm1] = vw1.y;
        Ws[0][lkq + 2][lm1] = vw1.z; Ws[0][lkq + 3][lm1] = vw1.w;
    }
    __syncthreads();

    const int NT = K / BK;   // 64 tiles
    for (int kt = 0; kt < NT; kt++) {
        const int cur = kt & 1;
        const bool have_next = (kt + 1 < NT);

        // Issue next tile's global loads BEFORE compute (latency overlap)
        float4 nva0, nva1, nvw0, nvw1;
        if (have_next) {
            const int kb = (kt + 1) * BK;
            nva0 = *(const float4*)(Arow0 + kb);
            nva1 = *(const float4*)(Arow1 + kb);
            nvw0 = *(const float4*)(Wrow0 + kb);
            nvw1 = *(const float4*)(Wrow1 + kb);
        }

        // Compute current tile
#pragma unroll
        for (int k = 0; k < BK; k++) {
            float a[8];
            *(float4*)(a)     = *(const float4*)&As[cur][k][tr * 8];
            *(float4*)(a + 4) = *(const float4*)&As[cur][k][tr * 8 + 4];
            ulonglong2 b01 = *(const ulonglong2*)&Ws[cur][k][tc * 8];
            ulonglong2 b23 = *(const ulonglong2*)&Ws[cur][k][tc * 8 + 4];
            u64t bu[4] = {b01.x, b01.y, b23.x, b23.y};
#pragma unroll
            for (int i = 0; i < 8; i++) {
                u64t pa = dup2(a[i]);
#pragma unroll
                for (int j = 0; j < 4; j++)
                    acc[i][j] = fma2(pa, bu[j], acc[i][j]);
            }
        }

        // Stage next tile into the other buffer; single barrier per iter
        if (have_next) {
            const int nb = 1 - cur;
            As[nb][lkq + 0][lm0] = nva0.x; As[nb][lkq + 1][lm0] = nva0.y;
            As[nb][lkq + 2][lm0] = nva0.z; As[nb][lkq + 3][lm0] = nva0.w;
            As[nb][lkq + 0][lm1] = nva1.x; As[nb][lkq + 1][lm1] = nva1.y;
            As[nb][lkq + 2][lm1] = nva1.z; As[nb][lkq + 3][lm1] = nva1.w;
            Ws[nb][lkq + 0][lm0] = nvw0.x; Ws[nb][lkq + 1][lm0] = nvw0.y;
            Ws[nb][lkq + 2][lm0] = nvw0.z; Ws[nb][lkq + 3][lm0] = nvw0.w;
            Ws[nb][lkq + 0][lm1] = nvw1.x; Ws[nb][lkq + 1][lm1] = nvw1.y;
            Ws[nb][lkq + 2][lm1] = nvw1.z; Ws[nb][lkq + 3][lm1] = nvw1.w;
            __syncthreads();
        }
    }

    // Epilogue: unpack, bias add, float4 stores
#pragma unroll
    for (int i = 0; i < 8; i++) {
        const int row = m0 + tr * 8 + i;
        float v[8];
#pragma unroll
        for (int j = 0; j < 4; j++) unpack2(acc[i][j], v[2 * j], v[2 * j + 1]);
        const int col = n0 + tc * 8;
        float4 o0, o1;
        o0.x = v[0] + bias[col + 0];
        o0.y = v[1] + bias[col + 1];
        o0.z = v[2] + bias[col + 2];
        o0.w = v[3] + bias[col + 3];
        o1.x = v[4] + bias[col + 4];
        o1.y = v[5] + bias[col + 5];
        o1.z = v[6] + bias[col + 6];
        o1.w = v[7] + bias[col + 7];
        *(float4*)(C + (size_t)row * N + col)     = o0;
        *(float4*)(C + (size_t)row * N + col + 4) = o1;
    }
}

// ---------------------------------------------------------------------------
// Flash attention (packed f32x2, bit-exact fp32): one CTA per (b*h, 64-row
// q tile). sm_scale = 1/8 folded into the Q load (power of two: exact).
// SMEM: Qst [d][row] (scaled Q^T), KP (K^T [d][kv] -> aliased as P [q][kv]),
// Vs [kv][d]. 52224 B dynamic. Unchanged from round 2.
// ---------------------------------------------------------------------------
#define AT_PAD 68   // row stride floats: 272B, 16B aligned

__global__ __launch_bounds__(256) void attn_kernel(
    const float* __restrict__ Q, const float* __restrict__ K,
    const float* __restrict__ V, float* __restrict__ O)
{
    extern __shared__ float smem[];
    float* Qst = smem;
    float* KP  = smem + 64 * AT_PAD;
    float* Vs  = smem + 2 * 64 * AT_PAD;

    const int tid = threadIdx.x;
    const int ty = tid >> 4;
    const int tx = tid & 15;
    const int q0 = blockIdx.x * 64;
    const int bh = blockIdx.y;
    const int b  = bh / H_;
    const int h  = bh % H_;

    const float* Qb = Q + (size_t)b * L_ * D_ + h * HD_;
    const float* Kb = K + (size_t)b * L_ * D_ + h * HD_;
    const float* Vb = V + (size_t)b * L_ * D_ + h * HD_;

    // Load Q tile transposed & pre-scaled by 1/8
#pragma unroll
    for (int t = 0; t < 4; t++) {
        int l   = tid + t * 256;
        int row = l >> 4;
        int dq  = (l & 15) << 2;
        float4 v = *(const float4*)(Qb + (size_t)(q0 + row) * D_ + dq);
        Qst[(dq + 0) * AT_PAD + row] = v.x * 0.125f;
        Qst[(dq + 1) * AT_PAD + row] = v.y * 0.125f;
        Qst[(dq + 2) * AT_PAD + row] = v.z * 0.125f;
        Qst[(dq + 3) * AT_PAD + row] = v.w * 0.125f;
    }

    float mi[4], li[4];
    u64t oacc[4][2];
#pragma unroll
    for (int i = 0; i < 4; i++) {
        mi[i] = -INFINITY;
        li[i] = 0.0f;
        oacc[i][0] = 0ull;
        oacc[i][1] = 0ull;
    }

    for (int kv0 = 0; kv0 < L_; kv0 += 64) {
        __syncthreads();  // previous iteration done reading KP / Vs

        // K tile transposed -> KP[d][kv]; V tile natural -> Vs[kv][d]
#pragma unroll
        for (int t = 0; t < 4; t++) {
            int l   = tid + t * 256;
            int row = l >> 4;
            int dq  = (l & 15) << 2;
            float4 kv = *(const float4*)(Kb + (size_t)(kv0 + row) * D_ + dq);
            KP[(dq + 0) * AT_PAD + row] = kv.x;
            KP[(dq + 1) * AT_PAD + row] = kv.y;
            KP[(dq + 2) * AT_PAD + row] = kv.z;
            KP[(dq + 3) * AT_PAD + row] = kv.w;
            float4 vv = *(const float4*)(Vb + (size_t)(kv0 + row) * D_ + dq);
            *(float4*)&Vs[row * AT_PAD + dq] = vv;
        }
        __syncthreads();

        // S = Qs K^T  (4 rows x 2 packed col-pairs per thread)
        u64t s2[4][2];
#pragma unroll
        for (int i = 0; i < 4; i++) { s2[i][0] = 0ull; s2[i][1] = 0ull; }

#pragma unroll
        for (int d = 0; d < 64; d++) {
            float a[4];
            *(float4*)a = *(const float4*)&Qst[d * AT_PAD + ty * 4];
            ulonglong2 bb = *(const ulonglong2*)&KP[d * AT_PAD + tx * 4];
#pragma unroll
            for (int i = 0; i < 4; i++) {
                u64t pa = dup2(a[i]);
                s2[i][0] = fma2(pa, bb.x, s2[i][0]);
                s2[i][1] = fma2(pa, bb.y, s2[i][1]);
            }
        }

        // Online softmax (unpacked, register + shuffle only)
        float s[4][4], scalef[4];
#pragma unroll
        for (int i = 0; i < 4; i++) {
            unpack2(s2[i][0], s[i][0], s[i][1]);
            unpack2(s2[i][1], s[i][2], s[i][3]);
            float v = fmaxf(fmaxf(s[i][0], s[i][1]), fmaxf(s[i][2], s[i][3]));
#pragma unroll
            for (int off = 8; off >= 1; off >>= 1)
                v = fmaxf(v, __shfl_xor_sync(0xffffffffu, v, off));
            float mnew = fmaxf(mi[i], v);
            scalef[i] = __expf(mi[i] - mnew);
#pragma unroll
            for (int j = 0; j < 4; j++) s[i][j] = __expf(s[i][j] - mnew);
            float r = (s[i][0] + s[i][1]) + (s[i][2] + s[i][3]);
#pragma unroll
            for (int off = 8; off >= 1; off >>= 1)
                r += __shfl_xor_sync(0xffffffffu, r, off);
            li[i] = li[i] * scalef[i] + r;
            mi[i] = mnew;
            u64t sc = dup2(scalef[i]);
            oacc[i][0] = mul2(oacc[i][0], sc);
            oacc[i][1] = mul2(oacc[i][1], sc);
        }

        __syncthreads();  // done reading KP as K^T

        // Write P over KP: P[qrow][kv]  (float4 stores)
#pragma unroll
        for (int i = 0; i < 4; i++)
            *(float4*)&KP[(ty * 4 + i) * AT_PAD + tx * 4] =
                make_float4(s[i][0], s[i][1], s[i][2], s[i][3]);
        __syncthreads();

        // O += P @ V  (packed along head-dim)
#pragma unroll
        for (int k = 0; k < 64; k++) {
            ulonglong2 bb = *(const ulonglong2*)&Vs[k * AT_PAD + tx * 4];
#pragma unroll
            for (int i = 0; i < 4; i++) {
                u64t pa = dup2(KP[(ty * 4 + i) * AT_PAD + k]);
                oacc[i][0] = fma2(pa, bb.x, oacc[i][0]);
                oacc[i][1] = fma2(pa, bb.y, oacc[i][1]);
            }
        }
    }

    // Epilogue: normalize, store into head-concat layout [B*L, D]
    float* Ob = O + (size_t)b * L_ * D_ + h * HD_;
#pragma unroll
    for (int i = 0; i < 4; i++) {
        const float inv = 1.0f / li[i];
        const int row = q0 + ty * 4 + i;
        float o0, o1, o2, o3;
        unpack2(oacc[i][0], o0, o1);
        unpack2(oacc[i][1], o2, o3);
        *(float4*)(Ob + (size_t)row * D_ + tx * 4) =
            make_float4(o0 * inv, o1 * inv, o2 * inv, o3 * inv);
    }
}

// ---------------------------------------------------------------------------
// Launch
// ---------------------------------------------------------------------------
extern "C" void kernel_launch(void* const* d_in, const int* in_sizes, int n_in,
                              void* d_out, int out_size)
{
    (void)in_sizes; (void)n_in; (void)out_size;
    const float* query = (const float*)d_in[0];
    const float* key   = (const float*)d_in[1];
    const float* value = (const float*)d_in[2];
    const float* Wq    = (const float*)d_in[3];
    const float* bq    = (const float*)d_in[4];
    const float* Wk    = (const float*)d_in[5];
    const float* bk    = (const float*)d_in[6];
    const float* Wv    = (const float*)d_in[7];
    const float* bv    = (const float*)d_in[8];
    const float* Wo    = (const float*)d_in[9];
    const float* bo    = (const float*)d_in[10];
    float* out = (float*)d_out;

    float *Qb, *Kb, *Vb, *Cb;
    cudaGetSymbolAddress((void**)&Qb, g_Q);
    cudaGetSymbolAddress((void**)&Kb, g_K);
    cudaGetSymbolAddress((void**)&Vb, g_V);
    cudaGetSymbolAddress((void**)&Cb, g_C);

    const int attn_smem = 3 * 64 * AT_PAD * 4;  // 52224 bytes
    cudaFuncSetAttribute(attn_kernel,
                         cudaFuncAttributeMaxDynamicSharedMemorySize, attn_smem);

    dim3 gemm_grid(D_ / BN, M_TOT / BM);  // (8, 64)
    gemm_f32x2_bias<<<gemm_grid, 256>>>(query, Wq, bq, Qb, M_TOT, D_, D_);
    gemm_f32x2_bias<<<gemm_grid, 256>>>(key,   Wk, bk, Kb, M_TOT, D_, D_);
    gemm_f32x2_bias<<<gemm_grid, 256>>>(value, Wv, bv, Vb, M_TOT, D_, D_);

    attn_kernel<<<dim3(L_ / 64, B_ * H_), 256, attn_smem>>>(Qb, Kb, Vb, Cb);

    gemm_f32x2_bias<<<gemm_grid, 2 * 256 / 2>>>(Cb, Wo, bo, out, M_TOT, D_, D_);
}

// round 6
// speedup vs baseline: 1.1560x; 1.1560x over previous
#include <cuda_runtime.h>
#include <cuda_bf16.h>
#include <math.h>
#include <stdint.h>

// Problem constants
#define B_  4
#define L_  2048
#define D_  1024
#define H_  16
#define HD_ 64
#define M_TOT (B_ * L_)          // 8192 rows for all projection GEMMs

typedef unsigned long long u64t;

// ---------------------------------------------------------------------------
// Scratch (allocation-free rule: __device__ globals)
// ---------------------------------------------------------------------------
__device__ float g_Q[(size_t)M_TOT * D_];
__device__ float g_K[(size_t)M_TOT * D_];
__device__ float g_V[(size_t)M_TOT * D_];
__device__ float g_C[(size_t)M_TOT * D_];

// ---------------------------------------------------------------------------
// Packed f32x2 helpers (GEMM path, bit-exact fp32)
// ---------------------------------------------------------------------------
__device__ __forceinline__ u64t fma2(u64t a, u64t b, u64t c) {
    u64t d;
    asm("fma.rn.f32x2 %0, %1, %2, %3;" : "=l"(d) : "l"(a), "l"(b), "l"(c));
    return d;
}
__device__ __forceinline__ u64t dup2(float x) {
    u64t d;
    uint32_t u = __float_as_uint(x);
    asm("mov.b64 %0, {%1, %2};" : "=l"(d) : "r"(u), "r"(u));
    return d;
}
__device__ __forceinline__ void unpack2(u64t v, float& lo, float& hi) {
    uint32_t a, b;
    asm("mov.b64 {%0, %1}, %2;" : "=r"(a), "=r"(b) : "l"(v));
    lo = __uint_as_float(a);
    hi = __uint_as_float(b);
}

// ---------------------------------------------------------------------------
// tf32 helpers (attention tensor-core path)
// ---------------------------------------------------------------------------
__device__ __forceinline__ float tf32r(float x) {   // round to tf32, as float
    uint32_t r;
    asm("cvt.rna.tf32.f32 %0, %1;" : "=r"(r) : "f"(x));
    return __uint_as_float(r);
}
__device__ __forceinline__ void mma_tf32(
    float& c0, float& c1, float& c2, float& c3,
    uint32_t a0, uint32_t a1, uint32_t a2, uint32_t a3,
    uint32_t b0, uint32_t b1)
{
    asm volatile(
        "mma.sync.aligned.m16n8k8.row.col.f32.tf32.tf32.f32 "
        "{%0,%1,%2,%3}, {%4,%5,%6,%7}, {%8,%9}, {%0,%1,%2,%3};\n"
        : "+f"(c0), "+f"(c1), "+f"(c2), "+f"(c3)
        : "r"(a0), "r"(a1), "r"(a2), "r"(a3), "r"(b0), "r"(b1));
}

// ---------------------------------------------------------------------------
// GEMM (packed f32x2, bit-exact fp32, double-buffered) — measured good.
// ---------------------------------------------------------------------------
#define BM 128
#define BN 128
#define BK 16
#define GST (BM + 4)

__global__ __launch_bounds__(256, 2) void gemm_f32x2_bias(
    const float* __restrict__ A, const float* __restrict__ W,
    const float* __restrict__ bias, float* __restrict__ C,
    int M, int N, int K)
{
    __shared__ float As[2][BK][GST];
    __shared__ float Ws[2][BK][GST];

    const int tid = threadIdx.x;
    const int m0 = blockIdx.y * BM;
    const int n0 = blockIdx.x * BN;
    const int tr = tid >> 4;
    const int tc = tid & 15;

    const int lm0 = tid >> 2;
    const int lm1 = (tid + 256) >> 2;
    const int lkq = (tid & 3) << 2;

    u64t acc[8][4];
#pragma unroll
    for (int i = 0; i < 8; i++)
#pragma unroll
        for (int j = 0; j < 4; j++) acc[i][j] = 0ull;

    const float* Arow0 = A + (size_t)(m0 + lm0) * K + lkq;
    const float* Arow1 = A + (size_t)(m0 + lm1) * K + lkq;
    const float* Wrow0 = W + (size_t)(n0 + lm0) * K + lkq;
    const float* Wrow1 = W + (size_t)(n0 + lm1) * K + lkq;

    {
        float4 va0 = *(const float4*)(Arow0);
        float4 va1 = *(const float4*)(Arow1);
        float4 vw0 = *(const float4*)(Wrow0);
        float4 vw1 = *(const float4*)(Wrow1);
        As[0][lkq + 0][lm0] = va0.x; As[0][lkq + 1][lm0] = va0.y;
        As[0][lkq + 2][lm0] = va0.z; As[0][lkq + 3][lm0] = va0.w;
        As[0][lkq + 0][lm1] = va1.x; As[0][lkq + 1][lm1] = va1.y;
        As[0][lkq + 2][lm1] = va1.z; As[0][lkq + 3][lm1] = va1.w;
        Ws[0][lkq + 0][lm0] = vw0.x; Ws[0][lkq + 1][lm0] = vw0.y;
        Ws[0][lkq + 2][lm0] = vw0.z; Ws[0][lkq + 3][lm0] = vw0.w;
        Ws[0][lkq + 0][lm1] = vw1.x; Ws[0][lkq + 1][lm1] = vw1.y;
        Ws[0][lkq + 2][lm1] = vw1.z; Ws[0][lkq + 3][lm1] = vw1.w;
    }
    __syncthreads();

    const int NT = K / BK;
    for (int kt = 0; kt < NT; kt++) {
        const int cur = kt & 1;
        const bool have_next = (kt + 1 < NT);

        float4 nva0, nva1, nvw0, nvw1;
        if (have_next) {
            const int kb = (kt + 1) * BK;
            nva0 = *(const float4*)(Arow0 + kb);
            nva1 = *(const float4*)(Arow1 + kb);
            nvw0 = *(const float4*)(Wrow0 + kb);
            nvw1 = *(const float4*)(Wrow1 + kb);
        }

#pragma unroll
        for (int k = 0; k < BK; k++) {
            float a[8];
            *(float4*)(a)     = *(const float4*)&As[cur][k][tr * 8];
            *(float4*)(a + 4) = *(const float4*)&As[cur][k][tr * 8 + 4];
            ulonglong2 b01 = *(const ulonglong2*)&Ws[cur][k][tc * 8];
            ulonglong2 b23 = *(const ulonglong2*)&Ws[cur][k][tc * 8 + 4];
            u64t bu[4] = {b01.x, b01.y, b23.x, b23.y};
#pragma unroll
            for (int i = 0; i < 8; i++) {
                u64t pa = dup2(a[i]);
#pragma unroll
                for (int j = 0; j < 4; j++)
                    acc[i][j] = fma2(pa, bu[j], acc[i][j]);
            }
        }

        if (have_next) {
            const int nb = 1 - cur;
            As[nb][lkq + 0][lm0] = nva0.x; As[nb][lkq + 1][lm0] = nva0.y;
            As[nb][lkq + 2][lm0] = nva0.z; As[nb][lkq + 3][lm0] = nva0.w;
            As[nb][lkq + 0][lm1] = nva1.x; As[nb][lkq + 1][lm1] = nva1.y;
            As[nb][lkq + 2][lm1] = nva1.z; As[nb][lkq + 3][lm1] = nva1.w;
            Ws[nb][lkq + 0][lm0] = nvw0.x; Ws[nb][lkq + 1][lm0] = nvw0.y;
            Ws[nb][lkq + 2][lm0] = nvw0.z; Ws[nb][lkq + 3][lm0] = nvw0.w;
            Ws[nb][lkq + 0][lm1] = nvw1.x; Ws[nb][lkq + 1][lm1] = nvw1.y;
            Ws[nb][lkq + 2][lm1] = nvw1.z; Ws[nb][lkq + 3][lm1] = nvw1.w;
            __syncthreads();
        }
    }

#pragma unroll
    for (int i = 0; i < 8; i++) {
        const int row = m0 + tr * 8 + i;
        float v[8];
#pragma unroll
        for (int j = 0; j < 4; j++) unpack2(acc[i][j], v[2 * j], v[2 * j + 1]);
        const int col = n0 + tc * 8;
        float4 o0, o1;
        o0.x = v[0] + bias[col + 0];
        o0.y = v[1] + bias[col + 1];
        o0.z = v[2] + bias[col + 2];
        o0.w = v[3] + bias[col + 3];
        o1.x = v[4] + bias[col + 4];
        o1.y = v[5] + bias[col + 5];
        o1.z = v[6] + bias[col + 6];
        o1.w = v[7] + bias[col + 7];
        *(float4*)(C + (size_t)row * N + col)     = o0;
        *(float4*)(C + (size_t)row * N + col + 4) = o1;
    }
}

// ---------------------------------------------------------------------------
// Flash attention on tensor cores: split-tf32 (hi/lo) mma.sync, fp32-accurate.
// CTA: 256 thr = 8 warps as (warp_m 0..3) x (warp_n 0..1).
// Tile: 64 q-rows x 64 kv per iteration; each warp: m16 x n32.
// S = Qs*K^T via hi*hi + hi*lo + lo*hi (error ~2^-22). PV likewise with P
// split at fragment load. sm_scale=1/8 folded into Q staging (exact).
// SMEM (floats, stride 68): Qhi,Qlo,Khi,Klo,Vhi,Vlo [64][68]; P aliases Khi;
// maxbuf/sumbuf [2][64]. Total 105472 B -> 2 CTAs/SM.
// ---------------------------------------------------------------------------
#define AST 68
#define ATILE 4352          // 64*68

__global__ __launch_bounds__(256) void attn_tc(
    const float* __restrict__ Q, const float* __restrict__ K,
    const float* __restrict__ V, float* __restrict__ O)
{
    extern __shared__ float sm[];
    float* Qhi = sm;
    float* Qlo = sm + ATILE;
    float* Khi = sm + 2 * ATILE;    // aliased as P after S-phase
    float* Klo = sm + 3 * ATILE;
    float* Vhi = sm + 4 * ATILE;
    float* Vlo = sm + 5 * ATILE;
    float* Pbuf = Khi;
    float* maxbuf = sm + 6 * ATILE;        // [2][64]
    float* sumbuf = maxbuf + 128;          // [2][64]

    const int tid  = threadIdx.x;
    const int warp = tid >> 5;
    const int lane = tid & 31;
    const int g    = lane >> 2;     // 0..7
    const int tig  = lane & 3;      // 0..3
    const int warp_m = warp >> 1;   // 0..3
    const int warp_n = warp & 1;    // 0..1
    const int m0 = warp_m * 16;
    const int nb = warp_n * 32;

    const int q0 = blockIdx.x * 64;
    const int bh = blockIdx.y;
    const int b  = bh / H_;
    const int h  = bh % H_;

    const float* Qb = Q + (size_t)b * L_ * D_ + h * HD_;
    const float* Kb = K + (size_t)b * L_ * D_ + h * HD_;
    const float* Vb = V + (size_t)b * L_ * D_ + h * HD_;

    // Stage Q once: pre-scale by 1/8 (exact), split hi/lo
#pragma unroll
    for (int t = 0; t < 4; t++) {
        int idx = tid + t * 256;
        int row = idx >> 4;
        int d0  = (idx & 15) << 2;
        float4 v = *(const float4*)(Qb + (size_t)(q0 + row) * D_ + d0);
        v.x *= 0.125f; v.y *= 0.125f; v.z *= 0.125f; v.w *= 0.125f;
        float4 hi = make_float4(tf32r(v.x), tf32r(v.y), tf32r(v.z), tf32r(v.w));
        float4 lo = make_float4(tf32r(v.x - hi.x), tf32r(v.y - hi.y),
                                tf32r(v.z - hi.z), tf32r(v.w - hi.w));
        *(float4*)&Qhi[row * AST + d0] = hi;
        *(float4*)&Qlo[row * AST + d0] = lo;
    }

    float mi0 = -INFINITY, mi1 = -INFINITY, li0 = 0.0f, li1 = 0.0f;
    float oacc[4][4];
#pragma unroll
    for (int nt = 0; nt < 4; nt++)
#pragma unroll
        for (int r = 0; r < 4; r++) oacc[nt][r] = 0.0f;

    for (int kv0 = 0; kv0 < L_; kv0 += 64) {
        __syncthreads();   // (A) prev PV fragment reads done

        // Stage K, V (split hi/lo)
#pragma unroll
        for (int t = 0; t < 4; t++) {
            int idx = tid + t * 256;
            int row = idx >> 4;
            int d0  = (idx & 15) << 2;
            float4 kv = *(const float4*)(Kb + (size_t)(kv0 + row) * D_ + d0);
            float4 khi = make_float4(tf32r(kv.x), tf32r(kv.y), tf32r(kv.z), tf32r(kv.w));
            float4 klo = make_float4(tf32r(kv.x - khi.x), tf32r(kv.y - khi.y),
                                     tf32r(kv.z - khi.z), tf32r(kv.w - khi.w));
            *(float4*)&Khi[row * AST + d0] = khi;
            *(float4*)&Klo[row * AST + d0] = klo;
            float4 vv = *(const float4*)(Vb + (size_t)(kv0 + row) * D_ + d0);
            float4 vhi = make_float4(tf32r(vv.x), tf32r(vv.y), tf32r(vv.z), tf32r(vv.w));
            float4 vlo = make_float4(tf32r(vv.x - vhi.x), tf32r(vv.y - vhi.y),
                                     tf32r(vv.z - vhi.z), tf32r(vv.w - vhi.w));
            *(float4*)&Vhi[row * AST + d0] = vhi;
            *(float4*)&Vlo[row * AST + d0] = vlo;
        }
        __syncthreads();   // (B) tiles staged

        // ---- S = Qs K^T (split: hh + hl + lh) ----
        float sacc[4][4];
#pragma unroll
        for (int nt = 0; nt < 4; nt++)
#pragma unroll
            for (int r = 0; r < 4; r++) sacc[nt][r] = 0.0f;

#pragma unroll
        for (int k8 = 0; k8 < 8; k8++) {
            const int kb = k8 * 8;
            const int ra = (m0 + g) * AST + kb + tig;
            const int rb = (m0 + g + 8) * AST + kb + tig;
            uint32_t ah0 = __float_as_uint(Qhi[ra]);
            uint32_t ah1 = __float_as_uint(Qhi[rb]);
            uint32_t ah2 = __float_as_uint(Qhi[ra + 4]);
            uint32_t ah3 = __float_as_uint(Qhi[rb + 4]);
            uint32_t al0 = __float_as_uint(Qlo[ra]);
            uint32_t al1 = __float_as_uint(Qlo[rb]);
            uint32_t al2 = __float_as_uint(Qlo[ra + 4]);
            uint32_t al3 = __float_as_uint(Qlo[rb + 4]);
#pragma unroll
            for (int nt = 0; nt < 4; nt++) {
                const int rn = (nb + nt * 8 + g) * AST + kb + tig;
                uint32_t bh0 = __float_as_uint(Khi[rn]);
                uint32_t bh1 = __float_as_uint(Khi[rn + 4]);
                uint32_t bl0 = __float_as_uint(Klo[rn]);
                uint32_t bl1 = __float_as_uint(Klo[rn + 4]);
                mma_tf32(sacc[nt][0], sacc[nt][1], sacc[nt][2], sacc[nt][3],
                         ah0, ah1, ah2, ah3, bh0, bh1);
                mma_tf32(sacc[nt][0], sacc[nt][1], sacc[nt][2], sacc[nt][3],
                         ah0, ah1, ah2, ah3, bl0, bl1);
                mma_tf32(sacc[nt][0], sacc[nt][1], sacc[nt][2], sacc[nt][3],
                         al0, al1, al2, al3, bh0, bh1);
            }
        }

        // ---- Online softmax across the two warp_n halves ----
        float mx0 = -INFINITY, mx1 = -INFINITY;
#pragma unroll
        for (int nt = 0; nt < 4; nt++) {
            mx0 = fmaxf(mx0, fmaxf(sacc[nt][0], sacc[nt][1]));
            mx1 = fmaxf(mx1, fmaxf(sacc[nt][2], sacc[nt][3]));
        }
        mx0 = fmaxf(mx0, __shfl_xor_sync(0xffffffffu, mx0, 1));
        mx0 = fmaxf(mx0, __shfl_xor_sync(0xffffffffu, mx0, 2));
        mx1 = fmaxf(mx1, __shfl_xor_sync(0xffffffffu, mx1, 1));
        mx1 = fmaxf(mx1, __shfl_xor_sync(0xffffffffu, mx1, 2));
        if (tig == 0) {
            maxbuf[warp_n * 64 + m0 + g]     = mx0;
            maxbuf[warp_n * 64 + m0 + g + 8] = mx1;
        }
        __syncthreads();   // (C) also: all S-phase Khi/Klo reads done

        const float mn0 = fmaxf(mi0, fmaxf(maxbuf[m0 + g], maxbuf[64 + m0 + g]));
        const float mn1 = fmaxf(mi1, fmaxf(maxbuf[m0 + g + 8], maxbuf[64 + m0 + g + 8]));
        const float sc0 = __expf(mi0 - mn0);
        const float sc1 = __expf(mi1 - mn1);
        mi0 = mn0; mi1 = mn1;

        float ps0 = 0.0f, ps1 = 0.0f;
#pragma unroll
        for (int nt = 0; nt < 4; nt++) {
            sacc[nt][0] = __expf(sacc[nt][0] - mn0);
            sacc[nt][1] = __expf(sacc[nt][1] - mn0);
            sacc[nt][2] = __expf(sacc[nt][2] - mn1);
            sacc[nt][3] = __expf(sacc[nt][3] - mn1);
            ps0 += sacc[nt][0] + sacc[nt][1];
            ps1 += sacc[nt][2] + sacc[nt][3];
        }
        ps0 += __shfl_xor_sync(0xffffffffu, ps0, 1);
        ps0 += __shfl_xor_sync(0xffffffffu, ps0, 2);
        ps1 += __shfl_xor_sync(0xffffffffu, ps1, 1);
        ps1 += __shfl_xor_sync(0xffffffffu, ps1, 2);
        if (tig == 0) {
            sumbuf[warp_n * 64 + m0 + g]     = ps0;
            sumbuf[warp_n * 64 + m0 + g + 8] = ps1;
        }

        // Write P (fp32) over Khi; rescale O accumulators
#pragma unroll
        for (int nt = 0; nt < 4; nt++) {
            const int pc = nb + nt * 8 + 2 * tig;
            *(float2*)&Pbuf[(m0 + g) * AST + pc]     = make_float2(sacc[nt][0], sacc[nt][1]);
            *(float2*)&Pbuf[(m0 + g + 8) * AST + pc] = make_float2(sacc[nt][2], sacc[nt][3]);
            oacc[nt][0] *= sc0; oacc[nt][1] *= sc0;
            oacc[nt][2] *= sc1; oacc[nt][3] *= sc1;
        }
        __syncthreads();   // (D) P fully written, sums ready

        li0 = li0 * sc0 + sumbuf[m0 + g] + sumbuf[64 + m0 + g];
        li1 = li1 * sc1 + sumbuf[m0 + g + 8] + sumbuf[64 + m0 + g + 8];

        // ---- O += P V (split P at load; V pre-split) ----
#pragma unroll
        for (int k8 = 0; k8 < 8; k8++) {
            const int kb = k8 * 8;
            float f0 = Pbuf[(m0 + g) * AST + kb + tig];
            float f1 = Pbuf[(m0 + g + 8) * AST + kb + tig];
            float f2 = Pbuf[(m0 + g) * AST + kb + tig + 4];
            float f3 = Pbuf[(m0 + g + 8) * AST + kb + tig + 4];
            float h0 = tf32r(f0), h1 = tf32r(f1), h2 = tf32r(f2), h3 = tf32r(f3);
            uint32_t ph0 = __float_as_uint(h0), ph1 = __float_as_uint(h1);
            uint32_t ph2 = __float_as_uint(h2), ph3 = __float_as_uint(h3);
            uint32_t pl0 = __float_as_uint(tf32r(f0 - h0));
            uint32_t pl1 = __float_as_uint(tf32r(f1 - h1));
            uint32_t pl2 = __float_as_uint(tf32r(f2 - h2));
            uint32_t pl3 = __float_as_uint(tf32r(f3 - h3));
#pragma unroll
            for (int nt = 0; nt < 4; nt++) {
                const int cn = nb + nt * 8 + g;
                uint32_t vh0 = __float_as_uint(Vhi[(kb + tig) * AST + cn]);
                uint32_t vh1 = __float_as_uint(Vhi[(kb + tig + 4) * AST + cn]);
                uint32_t vl0 = __float_as_uint(Vlo[(kb + tig) * AST + cn]);
                uint32_t vl1 = __float_as_uint(Vlo[(kb + tig + 4) * AST + cn]);
                mma_tf32(oacc[nt][0], oacc[nt][1], oacc[nt][2], oacc[nt][3],
                         ph0, ph1, ph2, ph3, vh0, vh1);
                mma_tf32(oacc[nt][0], oacc[nt][1], oacc[nt][2], oacc[nt][3],
                         ph0, ph1, ph2, ph3, vl0, vl1);
                mma_tf32(oacc[nt][0], oacc[nt][1], oacc[nt][2], oacc[nt][3],
                         pl0, pl1, pl2, pl3, vh0, vh1);
            }
        }
    }

    // Epilogue: normalize, store head-concat layout
    float* Ob = O + (size_t)b * L_ * D_ + h * HD_;
    const float inv0 = 1.0f / li0;
    const float inv1 = 1.0f / li1;
#pragma unroll
    for (int nt = 0; nt < 4; nt++) {
        const int col = nb + nt * 8 + 2 * tig;
        *(float2*)(Ob + (size_t)(q0 + m0 + g) * D_ + col) =
            make_float2(oacc[nt][0] * inv0, oacc[nt][1] * inv0);
        *(float2*)(Ob + (size_t)(q0 + m0 + g + 8) * D_ + col) =
            make_float2(oacc[nt][2] * inv1, oacc[nt][3] * inv1);
    }
}

// ---------------------------------------------------------------------------
// Launch
// ---------------------------------------------------------------------------
extern "C" void kernel_launch(void* const* d_in, const int* in_sizes, int n_in,
                              void* d_out, int out_size)
{
    (void)in_sizes; (void)n_in; (void)out_size;
    const float* query = (const float*)d_in[0];
    const float* key   = (const float*)d_in[1];
    const float* value = (const float*)d_in[2];
    const float* Wq    = (const float*)d_in[3];
    const float* bq    = (const float*)d_in[4];
    const float* Wk    = (const float*)d_in[5];
    const float* bk    = (const float*)d_in[6];
    const float* Wv    = (const float*)d_in[7];
    const float* bv    = (const float*)d_in[8];
    const float* Wo    = (const float*)d_in[9];
    const float* bo    = (const float*)d_in[10];
    float* out = (float*)d_out;

    float *Qb, *Kb, *Vb, *Cb;
    cudaGetSymbolAddress((void**)&Qb, g_Q);
    cudaGetSymbolAddress((void**)&Kb, g_K);
    cudaGetSymbolAddress((void**)&Vb, g_V);
    cudaGetSymbolAddress((void**)&Cb, g_C);

    const int attn_smem = (6 * ATILE + 256) * 4;   // 105472 bytes
    cudaFuncSetAttribute(attn_tc,
                         cudaFuncAttributeMaxDynamicSharedMemorySize, attn_smem);

    dim3 gemm_grid(D_ / BN, M_TOT / BM);  // (8, 64)
    gemm_f32x2_bias<<<gemm_grid, 256>>>(query, Wq, bq, Qb, M_TOT, D_, D_);
    gemm_f32x2_bias<<<gemm_grid, 256>>>(key,   Wk, bk, Kb, M_TOT, D_, D_);
    gemm_f32x2_bias<<<gemm_grid, 256>>>(value, Wv, bv, Vb, M_TOT, D_, D_);

    attn_tc<<<dim3(L_ / 64, B_ * H_), 256, attn_smem>>>(Qb, Kb, Vb, Cb);

    gemm_f32x2_bias<<<gemm_grid, 256>>>(Cb, Wo, bo, out, M_TOT, D_, D_);
}

// round 8
// speedup vs baseline: 1.3010x; 1.1254x over previous
#include <cuda_runtime.h>
#include <cuda_bf16.h>
#include <math.h>
#include <stdint.h>

// Problem constants
#define B_  4
#define L_  2048
#define D_  1024
#define H_  16
#define HD_ 64
#define M_TOT (B_ * L_)          // 8192 rows for all projection GEMMs

// ---------------------------------------------------------------------------
// Scratch (allocation-free rule: __device__ globals)
// ---------------------------------------------------------------------------
__device__ float g_Q[(size_t)M_TOT * D_];
__device__ float g_K[(size_t)M_TOT * D_];
__device__ float g_V[(size_t)M_TOT * D_];
__device__ float g_C[(size_t)M_TOT * D_];

// ---------------------------------------------------------------------------
// tf32 helpers (shared by GEMM + attention tensor-core paths)
// ---------------------------------------------------------------------------
__device__ __forceinline__ float tf32r(float x) {   // round to tf32, as float
    uint32_t r;
    asm("cvt.rna.tf32.f32 %0, %1;" : "=r"(r) : "f"(x));
    return __uint_as_float(r);
}
__device__ __forceinline__ void mma_tf32(
    float& c0, float& c1, float& c2, float& c3,
    uint32_t a0, uint32_t a1, uint32_t a2, uint32_t a3,
    uint32_t b0, uint32_t b1)
{
    asm volatile(
        "mma.sync.aligned.m16n8k8.row.col.f32.tf32.tf32.f32 "
        "{%0,%1,%2,%3}, {%4,%5,%6,%7}, {%8,%9}, {%0,%1,%2,%3};\n"
        : "+f"(c0), "+f"(c1), "+f"(c2), "+f"(c3)
        : "r"(a0), "r"(a1), "r"(a2), "r"(a3), "r"(b0), "r"(b1));
}

// ---------------------------------------------------------------------------
// GEMM on tensor cores, split-tf32 (hh + hl + lh), fp32-level accuracy.
//   C[m][n] = sum_k A[m][k] * W[n][k] + bias[n]
// CTA tile 128x128, BK=16; 256 threads = 8 warps (warp_m 0..1 x warp_n 0..3),
// warp tile 64x32 via 4x4 grid of m16n8k8 MMAs, 3 MMAs per tile (split).
// Double-buffered dynamic SMEM: Ahi/Alo/Whi/Wlo [2][128][TST], 81920 B.
// Fragment LDS banks: 20*g + tig (+k) all-distinct -> conflict-free.
// ---------------------------------------------------------------------------
#define TST 20                    // SMEM row stride in floats (16 + 4 pad)
#define GBUF (128 * TST)          // floats per stage per matrix = 2560

__global__ __launch_bounds__(256, 2) void gemm_tf32s_bias(
    const float* __restrict__ A, const float* __restrict__ W,
    const float* __restrict__ bias, float* __restrict__ C,
    int M, int N, int K)
{
    extern __shared__ float dsm[];
    float* Ahi = dsm;                 // [2][GBUF]
    float* Alo = dsm + 2 * GBUF;
    float* Whi = dsm + 4 * GBUF;
    float* Wlo = dsm + 6 * GBUF;

    const int tid    = threadIdx.x;
    const int warp   = tid >> 5;
    const int lane   = tid & 31;
    const int g      = lane >> 2;    // 0..7
    const int tig    = lane & 3;     // 0..3
    const int warp_m = warp >> 2;    // 0..1 -> 64-row slab
    const int warp_n = warp & 3;     // 0..3 -> 32-col slab

    const int m0 = blockIdx.y * 128;
    const int n0 = blockIdx.x * 128;

    // Staging coords: 512 float4 per matrix per tile, 2 per thread
    const int lrow0 = tid >> 2;            // 0..63
    const int lrow1 = lrow0 + 64;          // 64..127
    const int lkq   = (tid & 3) << 2;      // 0,4,8,12

    const float* Ar0 = A + (size_t)(m0 + lrow0) * K + lkq;
    const float* Ar1 = A + (size_t)(m0 + lrow1) * K + lkq;
    const float* Wr0 = W + (size_t)(n0 + lrow0) * K + lkq;
    const float* Wr1 = W + (size_t)(n0 + lrow1) * K + lkq;

    float c[4][4][4];
#pragma unroll
    for (int i = 0; i < 4; i++)
#pragma unroll
        for (int j = 0; j < 4; j++)
#pragma unroll
            for (int r = 0; r < 4; r++) c[i][j][r] = 0.0f;

    // Split+store one float4 into hi/lo SMEM at (row, kq)
#define SPLIT_STORE(HI, LO, st, row, kq, v)                                   \
    do {                                                                      \
        float4 _h = make_float4(tf32r((v).x), tf32r((v).y),                   \
                                tf32r((v).z), tf32r((v).w));                  \
        (HI)[(st) * GBUF + (row) * TST + (kq) + 0] = _h.x;                    \
        (HI)[(st) * GBUF + (row) * TST + (kq) + 1] = _h.y;                    \
        (HI)[(st) * GBUF + (row) * TST + (kq) + 2] = _h.z;                    \
        (HI)[(st) * GBUF + (row) * TST + (kq) + 3] = _h.w;                    \
        (LO)[(st) * GBUF + (row) * TST + (kq) + 0] = tf32r((v).x - _h.x);     \
        (LO)[(st) * GBUF + (row) * TST + (kq) + 1] = tf32r((v).y - _h.y);     \
        (LO)[(st) * GBUF + (row) * TST + (kq) + 2] = tf32r((v).z - _h.z);     \
        (LO)[(st) * GBUF + (row) * TST + (kq) + 3] = tf32r((v).w - _h.w);     \
    } while (0)

    // Prologue: stage tile 0
    {
        float4 a0 = *(const float4*)(Ar0);
        float4 a1 = *(const float4*)(Ar1);
        float4 w0 = *(const float4*)(Wr0);
        float4 w1 = *(const float4*)(Wr1);
        SPLIT_STORE(Ahi, Alo, 0, lrow0, lkq, a0);
        SPLIT_STORE(Ahi, Alo, 0, lrow1, lkq, a1);
        SPLIT_STORE(Whi, Wlo, 0, lrow0, lkq, w0);
        SPLIT_STORE(Whi, Wlo, 0, lrow1, lkq, w1);
    }
    __syncthreads();

    const int NT = K / 16;   // 64 tiles
    for (int kt = 0; kt < NT; kt++) {
        const int cur = kt & 1;
        const bool have_next = (kt + 1 < NT);

        float4 na0, na1, nw0, nw1;
        if (have_next) {
            const int kb = (kt + 1) * 16;
            na0 = *(const float4*)(Ar0 + kb);
            na1 = *(const float4*)(Ar1 + kb);
            nw0 = *(const float4*)(Wr0 + kb);
            nw1 = *(const float4*)(Wr1 + kb);
        }

        // Two k-steps of 8
#pragma unroll
        for (int ks = 0; ks < 2; ks++) {
            const int k = ks * 8;
            uint32_t ah[4][4], al[4][4];
#pragma unroll
            for (int mt = 0; mt < 4; mt++) {
                const int r = warp_m * 64 + mt * 16 + g;
                const int ba = cur * GBUF + r * TST + k + tig;
                ah[mt][0] = __float_as_uint(Ahi[ba]);
                ah[mt][1] = __float_as_uint(Ahi[ba + 8 * TST]);
                ah[mt][2] = __float_as_uint(Ahi[ba + 4]);
                ah[mt][3] = __float_as_uint(Ahi[ba + 8 * TST + 4]);
                al[mt][0] = __float_as_uint(Alo[ba]);
                al[mt][1] = __float_as_uint(Alo[ba + 8 * TST]);
                al[mt][2] = __float_as_uint(Alo[ba + 4]);
                al[mt][3] = __float_as_uint(Alo[ba + 8 * TST + 4]);
            }
#pragma unroll
            for (int nt = 0; nt < 4; nt++) {
                const int n = warp_n * 32 + nt * 8 + g;
                const int bb = cur * GBUF + n * TST + k + tig;
                uint32_t bh0 = __float_as_uint(Whi[bb]);
                uint32_t bh1 = __float_as_uint(Whi[bb + 4]);
                uint32_t bl0 = __float_as_uint(Wlo[bb]);
                uint32_t bl1 = __float_as_uint(Wlo[bb + 4]);
#pragma unroll
                for (int mt = 0; mt < 4; mt++) {
                    mma_tf32(c[mt][nt][0], c[mt][nt][1], c[mt][nt][2], c[mt][nt][3],
                             ah[mt][0], ah[mt][1], ah[mt][2], ah[mt][3], bh0, bh1);
                    mma_tf32(c[mt][nt][0], c[mt][nt][1], c[mt][nt][2], c[mt][nt][3],
                             ah[mt][0], ah[mt][1], ah[mt][2], ah[mt][3], bl0, bl1);
                    mma_tf32(c[mt][nt][0], c[mt][nt][1], c[mt][nt][2], c[mt][nt][3],
                             al[mt][0], al[mt][1], al[mt][2], al[mt][3], bh0, bh1);
                }
            }
        }

        if (have_next) {
            const int nbuf = 1 - cur;
            SPLIT_STORE(Ahi, Alo, nbuf, lrow0, lkq, na0);
            SPLIT_STORE(Ahi, Alo, nbuf, lrow1, lkq, na1);
            SPLIT_STORE(Whi, Wlo, nbuf, lrow0, lkq, nw0);
            SPLIT_STORE(Whi, Wlo, nbuf, lrow1, lkq, nw1);
            __syncthreads();
        }
    }

    // Epilogue: bias add + float2 stores (audited round-2 mapping)
#pragma unroll
    for (int nt = 0; nt < 4; nt++) {
        const int col = n0 + warp_n * 32 + nt * 8 + 2 * tig;
        const float b0v = bias[col];
        const float b1v = bias[col + 1];
#pragma unroll
        for (int mt = 0; mt < 4; mt++) {
            const int row = m0 + warp_m * 64 + mt * 16 + g;
            *(float2*)(C + (size_t)row * N + col) =
                make_float2(c[mt][nt][0] + b0v, c[mt][nt][1] + b1v);
            *(float2*)(C + (size_t)(row + 8) * N + col) =
                make_float2(c[mt][nt][2] + b0v, c[mt][nt][3] + b1v);
        }
    }
#undef SPLIT_STORE
}

// ---------------------------------------------------------------------------
// Flash attention on tensor cores: split-tf32 mma.sync — UNCHANGED from the
// measured round-6 kernel (3018us, rel_err 1.49e-5).
// ---------------------------------------------------------------------------
#define AST 68
#define ATILE 4352          // 64*68

__global__ __launch_bounds__(256) void attn_tc(
    const float* __restrict__ Q, const float* __restrict__ K,
    const float* __restrict__ V, float* __restrict__ O)
{
    extern __shared__ float sm[];
    float* Qhi = sm;
    float* Qlo = sm + ATILE;
    float* Khi = sm + 2 * ATILE;    // aliased as P after S-phase
    float* Klo = sm + 3 * ATILE;
    float* Vhi = sm + 4 * ATILE;
    float* Vlo = sm + 5 * ATILE;
    float* Pbuf = Khi;
    float* maxbuf = sm + 6 * ATILE;        // [2][64]
    float* sumbuf = maxbuf + 128;          // [2][64]

    const int tid  = threadIdx.x;
    const int warp = tid >> 5;
    const int lane = tid & 31;
    const int g    = lane >> 2;
    const int tig  = lane & 3;
    const int warp_m = warp >> 1;
    const int warp_n = warp & 1;
    const int m0 = warp_m * 16;
    const int nb = warp_n * 32;

    const int q0 = blockIdx.x * 64;
    const int bh = blockIdx.y;
    const int b  = bh / H_;
    const int h  = bh % H_;

    const float* Qb = Q + (size_t)b * L_ * D_ + h * HD_;
    const float* Kb = K + (size_t)b * L_ * D_ + h * HD_;
    const float* Vb = V + (size_t)b * L_ * D_ + h * HD_;

#pragma unroll
    for (int t = 0; t < 4; t++) {
        int idx = tid + t * 256;
        int row = idx >> 4;
        int d0  = (idx & 15) << 2;
        float4 v = *(const float4*)(Qb + (size_t)(q0 + row) * D_ + d0);
        v.x *= 0.125f; v.y *= 0.125f; v.z *= 0.125f; v.w *= 0.125f;
        float4 hi = make_float4(tf32r(v.x), tf32r(v.y), tf32r(v.z), tf32r(v.w));
        float4 lo = make_float4(tf32r(v.x - hi.x), tf32r(v.y - hi.y),
                                tf32r(v.z - hi.z), tf32r(v.w - hi.w));
        *(float4*)&Qhi[row * AST + d0] = hi;
        *(float4*)&Qlo[row * AST + d0] = lo;
    }

    float mi0 = -INFINITY, mi1 = -INFINITY, li0 = 0.0f, li1 = 0.0f;
    float oacc[4][4];
#pragma unroll
    for (int nt = 0; nt < 4; nt++)
#pragma unroll
        for (int r = 0; r < 4; r++) oacc[nt][r] = 0.0f;

    for (int kv0 = 0; kv0 < L_; kv0 += 64) {
        __syncthreads();   // (A)

#pragma unroll
        for (int t = 0; t < 4; t++) {
            int idx = tid + t * 256;
            int row = idx >> 4;
            int d0  = (idx & 15) << 2;
            float4 kv = *(const float4*)(Kb + (size_t)(kv0 + row) * D_ + d0);
            float4 khi = make_float4(tf32r(kv.x), tf32r(kv.y), tf32r(kv.z), tf32r(kv.w));
            float4 klo = make_float4(tf32r(kv.x - khi.x), tf32r(kv.y - khi.y),
                                     tf32r(kv.z - khi.z), tf32r(kv.w - khi.w));
            *(float4*)&Khi[row * AST + d0] = khi;
            *(float4*)&Klo[row * AST + d0] = klo;
            float4 vv = *(const float4*)(Vb + (size_t)(kv0 + row) * D_ + d0);
            float4 vhi = make_float4(tf32r(vv.x), tf32r(vv.y), tf32r(vv.z), tf32r(vv.w));
            float4 vlo = make_float4(tf32r(vv.x - vhi.x), tf32r(vv.y - vhi.y),
                                     tf32r(vv.z - vhi.z), tf32r(vv.w - vhi.w));
            *(float4*)&Vhi[row * AST + d0] = vhi;
            *(float4*)&Vlo[row * AST + d0] = vlo;
        }
        __syncthreads();   // (B)

        float sacc[4][4];
#pragma unroll
        for (int nt = 0; nt < 4; nt++)
#pragma unroll
            for (int r = 0; r < 4; r++) sacc[nt][r] = 0.0f;

#pragma unroll
        for (int k8 = 0; k8 < 8; k8++) {
            const int kb = k8 * 8;
            const int ra = (m0 + g) * AST + kb + tig;
            const int rb = (m0 + g + 8) * AST + kb + tig;
            uint32_t ah0 = __float_as_uint(Qhi[ra]);
            uint32_t ah1 = __float_as_uint(Qhi[rb]);
            uint32_t ah2 = __float_as_uint(Qhi[ra + 4]);
            uint32_t ah3 = __float_as_uint(Qhi[rb + 4]);
            uint32_t al0 = __float_as_uint(Qlo[ra]);
            uint32_t al1 = __float_as_uint(Qlo[rb]);
            uint32_t al2 = __float_as_uint(Qlo[ra + 4]);
            uint32_t al3 = __float_as_uint(Qlo[rb + 4]);
#pragma unroll
            for (int nt = 0; nt < 4; nt++) {
                const int rn = (nb + nt * 8 + g) * AST + kb + tig;
                uint32_t bh0 = __float_as_uint(Khi[rn]);
                uint32_t bh1 = __float_as_uint(Khi[rn + 4]);
                uint32_t bl0 = __float_as_uint(Klo[rn]);
                uint32_t bl1 = __float_as_uint(Klo[rn + 4]);
                mma_tf32(sacc[nt][0], sacc[nt][1], sacc[nt][2], sacc[nt][3],
                         ah0, ah1, ah2, ah3, bh0, bh1);
                mma_tf32(sacc[nt][0], sacc[nt][1], sacc[nt][2], sacc[nt][3],
                         ah0, ah1, ah2, ah3, bl0, bl1);
                mma_tf32(sacc[nt][0], sacc[nt][1], sacc[nt][2], sacc[nt][3],
                         al0, al1, al2, al3, bh0, bh1);
            }
        }

        float mx0 = -INFINITY, mx1 = -INFINITY;
#pragma unroll
        for (int nt = 0; nt < 4; nt++) {
            mx0 = fmaxf(mx0, fmaxf(sacc[nt][0], sacc[nt][1]));
            mx1 = fmaxf(mx1, fmaxf(sacc[nt][2], sacc[nt][3]));
        }
        mx0 = fmaxf(mx0, __shfl_xor_sync(0xffffffffu, mx0, 1));
        mx0 = fmaxf(mx0, __shfl_xor_sync(0xffffffffu, mx0, 2));
        mx1 = fmaxf(mx1, __shfl_xor_sync(0xffffffffu, mx1, 1));
        mx1 = fmaxf(mx1, __shfl_xor_sync(0xffffffffu, mx1, 2));
        if (tig == 0) {
            maxbuf[warp_n * 64 + m0 + g]     = mx0;
            maxbuf[warp_n * 64 + m0 + g + 8] = mx1;
        }
        __syncthreads();   // (C)

        const float mn0 = fmaxf(mi0, fmaxf(maxbuf[m0 + g], maxbuf[64 + m0 + g]));
        const float mn1 = fmaxf(mi1, fmaxf(maxbuf[m0 + g + 8], maxbuf[64 + m0 + g + 8]));
        const float sc0 = __expf(mi0 - mn0);
        const float sc1 = __expf(mi1 - mn1);
        mi0 = mn0; mi1 = mn1;

        float ps0 = 0.0f, ps1 = 0.0f;
#pragma unroll
        for (int nt = 0; nt < 4; nt++) {
            sacc[nt][0] = __expf(sacc[nt][0] - mn0);
            sacc[nt][1] = __expf(sacc[nt][1] - mn0);
            sacc[nt][2] = __expf(sacc[nt][2] - mn1);
            sacc[nt][3] = __expf(sacc[nt][3] - mn1);
            ps0 += sacc[nt][0] + sacc[nt][1];
            ps1 += sacc[nt][2] + sacc[nt][3];
        }
        ps0 += __shfl_xor_sync(0xffffffffu, ps0, 1);
        ps0 += __shfl_xor_sync(0xffffffffu, ps0, 2);
        ps1 += __shfl_xor_sync(0xffffffffu, ps1, 1);
        ps1 += __shfl_xor_sync(0xffffffffu, ps1, 2);
        if (tig == 0) {
            sumbuf[warp_n * 64 + m0 + g]     = ps0;
            sumbuf[warp_n * 64 + m0 + g + 8] = ps1;
        }

#pragma unroll
        for (int nt = 0; nt < 4; nt++) {
            const int pc = nb + nt * 8 + 2 * tig;
            *(float2*)&Pbuf[(m0 + g) * AST + pc]     = make_float2(sacc[nt][0], sacc[nt][1]);
            *(float2*)&Pbuf[(m0 + g + 8) * AST + pc] = make_float2(sacc[nt][2], sacc[nt][3]);
            oacc[nt][0] *= sc0; oacc[nt][1] *= sc0;
            oacc[nt][2] *= sc1; oacc[nt][3] *= sc1;
        }
        __syncthreads();   // (D)

        li0 = li0 * sc0 + sumbuf[m0 + g] + sumbuf[64 + m0 + g];
        li1 = li1 * sc1 + sumbuf[m0 + g + 8] + sumbuf[64 + m0 + g + 8];

#pragma unroll
        for (int k8 = 0; k8 < 8; k8++) {
            const int kb = k8 * 8;
            float f0 = Pbuf[(m0 + g) * AST + kb + tig];
            float f1 = Pbuf[(m0 + g + 8) * AST + kb + tig];
            float f2 = Pbuf[(m0 + g) * AST + kb + tig + 4];
            float f3 = Pbuf[(m0 + g + 8) * AST + kb + tig + 4];
            float h0 = tf32r(f0), h1 = tf32r(f1), h2 = tf32r(f2), h3 = tf32r(f3);
            uint32_t ph0 = __float_as_uint(h0), ph1 = __float_as_uint(h1);
            uint32_t ph2 = __float_as_uint(h2), ph3 = __float_as_uint(h3);
            uint32_t pl0 = __float_as_uint(tf32r(f0 - h0));
            uint32_t pl1 = __float_as_uint(tf32r(f1 - h1));
            uint32_t pl2 = __float_as_uint(tf32r(f2 - h2));
            uint32_t pl3 = __float_as_uint(tf32r(f3 - h3));
#pragma unroll
            for (int nt = 0; nt < 4; nt++) {
                const int cn = nb + nt * 8 + g;
                uint32_t vh0 = __float_as_uint(Vhi[(kb + tig) * AST + cn]);
                uint32_t vh1 = __float_as_uint(Vhi[(kb + tig + 4) * AST + cn]);
                uint32_t vl0 = __float_as_uint(Vlo[(kb + tig) * AST + cn]);
                uint32_t vl1 = __float_as_uint(Vlo[(kb + tig + 4) * AST + cn]);
                mma_tf32(oacc[nt][0], oacc[nt][1], oacc[nt][2], oacc[nt][3],
                         ph0, ph1, ph2, ph3, vh0, vh1);
                mma_tf32(oacc[nt][0], oacc[nt][1], oacc[nt][2], oacc[nt][3],
                         ph0, ph1, ph2, ph3, vl0, vl1);
                mma_tf32(oacc[nt][0], oacc[nt][1], oacc[nt][2], oacc[nt][3],
                         pl0, pl1, pl2, pl3, vh0, vh1);
            }
        }
    }

    float* Ob = O + (size_t)b * L_ * D_ + h * HD_;
    const float inv0 = 1.0f / li0;
    const float inv1 = 1.0f / li1;
#pragma unroll
    for (int nt = 0; nt < 4; nt++) {
        const int col = nb + nt * 8 + 2 * tig;
        *(float2*)(Ob + (size_t)(q0 + m0 + g) * D_ + col) =
            make_float2(oacc[nt][0] * inv0, oacc[nt][1] * inv0);
        *(float2*)(Ob + (size_t)(q0 + m0 + g + 8) * D_ + col) =
            make_float2(oacc[nt][2] * inv1, oacc[nt][3] * inv1);
    }
}

// ---------------------------------------------------------------------------
// Launch
// ---------------------------------------------------------------------------
extern "C" void kernel_launch(void* const* d_in, const int* in_sizes, int n_in,
                              void* d_out, int out_size)
{
    (void)in_sizes; (void)n_in; (void)out_size;
    const float* query = (const float*)d_in[0];
    const float* key   = (const float*)d_in[1];
    const float* value = (const float*)d_in[2];
    const float* Wq    = (const float*)d_in[3];
    const float* bq    = (const float*)d_in[4];
    const float* Wk    = (const float*)d_in[5];
    const float* bk    = (const float*)d_in[6];
    const float* Wv    = (const float*)d_in[7];
    const float* bv    = (const float*)d_in[8];
    const float* Wo    = (const float*)d_in[9];
    const float* bo    = (const float*)d_in[10];
    float* out = (float*)d_out;

    float *Qb, *Kb, *Vb, *Cb;
    cudaGetSymbolAddress((void**)&Qb, g_Q);
    cudaGetSymbolAddress((void**)&Kb, g_K);
    cudaGetSymbolAddress((void**)&Vb, g_V);
    cudaGetSymbolAddress((void**)&Cb, g_C);

    const int gemm_smem = 8 * GBUF * 4;            // 81920 bytes
    cudaFuncSetAttribute(gemm_tf32s_bias,
                         cudaFuncAttributeMaxDynamicSharedMemorySize, gemm_smem);
    const int attn_smem = (6 * ATILE + 256) * 4;   // 105472 bytes
    cudaFuncSetAttribute(attn_tc,
                         cudaFuncAttributeMaxDynamicSharedMemorySize, attn_smem);

    dim3 gemm_grid(D_ / 128, M_TOT / 128);  // (8, 64)
    gemm_tf32s_bias<<<gemm_grid, 256, gemm_smem>>>(query, Wq, bq, Qb, M_TOT, D_, D_);
    gemm_tf32s_bias<<<gemm_grid, 256, gemm_smem>>>(key,   Wk, bk, Kb, M_TOT, D_, D_);
    gemm_tf32s_bias<<<gemm_grid, 256, gemm_smem>>>(value, Wv, bv, Vb, M_TOT, D_, D_);

    attn_tc<<<dim3(L_ / 64, B_ * H_), 256, attn_smem>>>(Qb, Kb, Vb, Cb);

    gemm_tf32s_bias<<<gemm_grid, 256, gemm_smem>>>(Cb, Wo, bo, out, M_TOT, D_, D_);
}